// round 6
// baseline (speedup 1.0000x reference)
#include <cuda_runtime.h>

// SIREN: N pts, 3 -> 5 (sine) -> 256 x [5 -> 5 (sine)] -> 1 linear.
// Output: [out (N) | coords passthrough (3N)].
// 4 pts/thread as 2 f32x2 streams, software-pipelined with a ONE-LAYER SKEW:
// stream B runs one layer behind A so each MUFU sine burst overlaps the other
// stream's FFMA2 matvec burst (breaks MUFU/FMA phase alternation).

typedef unsigned long long u64;
typedef unsigned int u32;

static constexpr int IN_F  = 3;
static constexpr int HID   = 5;
static constexpr int N_HID = 256;
static constexpr float OMEGA = 30.0f;
static constexpr int TPB = 256;

// smem: [0, 51200) 256 layers x 25 w dup-pairs (u64); [51200, 56320) 256 x 5 bias scalars
static constexpr int BLOB_U64   = N_HID * 25;
static constexpr int SMEM_BYTES = BLOB_U64 * 8 + N_HID * 5 * 4;   // 56320

__device__ __forceinline__ u64 fma2(u64 a, u64 b, u64 c) {
    u64 d; asm("fma.rn.f32x2 %0, %1, %2, %3;" : "=l"(d) : "l"(a), "l"(b), "l"(c)); return d;
}
__device__ __forceinline__ u64 add2(u64 a, u64 b) {
    u64 d; asm("add.rn.f32x2 %0, %1, %2;" : "=l"(d) : "l"(a), "l"(b)); return d;
}
__device__ __forceinline__ u64 pack2(float a, float b) {
    u64 d; asm("mov.b64 %0, {%1, %2};" : "=l"(d) : "f"(a), "f"(b)); return d;
}
__device__ __forceinline__ u64 splat2(float a) {
    u64 d; asm("mov.b64 %0, {%1, %1};" : "=l"(d) : "f"(a)); return d;
}
__device__ __forceinline__ float2 unpack2(u64 d) {
    float2 f; asm("mov.b64 {%0, %1}, %2;" : "=f"(f.x), "=f"(f.y) : "l"(d)); return f;
}
__device__ __forceinline__ float sinap(float x) {
    float s; asm("sin.approx.f32 %0, %1;" : "=f"(s) : "f"(x)); return s;
}

struct SinK { u64 magic, nmagic, inv2pi, n2pi; };

// sin of both lanes: 1-term CW reduction mod 2pi into [-pi,pi], MUFU sine.
__device__ __forceinline__ u64 sin2m(u64 y, const SinK& K) {
    u64 t  = fma2(y, K.inv2pi, K.magic);
    u64 fj = add2(t, K.nmagic);
    u64 r  = fma2(fj, K.n2pi, y);
    float2 rf = unpack2(r);
    return pack2(sinap(rf.x), sinap(rf.y));
}

// x[5] = sin(y[5])
__device__ __forceinline__ void sin5(u64* __restrict__ x, const u64* __restrict__ y,
                                     const SinK& K) {
#pragma unroll
    for (int j = 0; j < HID; j++) x[j] = sin2m(y[j], K);
}

// y[5] = W * x[5] + b   (W: 25 dup-pairs k-major, b: 5 scalars)
__device__ __forceinline__ void matvec5(u64* __restrict__ y, const u64* __restrict__ x,
                                        const u64* __restrict__ L,
                                        const float* __restrict__ Bv) {
#pragma unroll
    for (int j = 0; j < HID; j++) y[j] = fma2(L[j], x[0], splat2(Bv[j]));
#pragma unroll
    for (int k = 1; k < HID; k++) {
#pragma unroll
        for (int j = 0; j < HID; j++) y[j] = fma2(L[k * 5 + j], x[k], y[j]);
    }
}

__global__ void __launch_bounds__(TPB, 4)
siren_kernel(const float* __restrict__ coords,
             const float* __restrict__ Wf, const float* __restrict__ bf,
             const float* __restrict__ Wh, const float* __restrict__ bh,
             const float* __restrict__ Wl, const float* __restrict__ bl,
             float* __restrict__ out, int N)
{
    extern __shared__ float smem[];
    u64*   wp = (u64*)smem;                  // 25 pairs/layer
    float* bp = smem + BLOB_U64 * 2;         // 5 scalars/layer

    const int tid = threadIdx.x;
    for (int idx = tid; idx < N_HID * 25; idx += TPB) {
        int l = idx / 25, r = idx % 25;
        int j = r / 5, k = r % 5;
        wp[l * 25 + k * 5 + j] = splat2(OMEGA * Wh[l * 25 + j * 5 + k]);
    }
    for (int idx = tid; idx < N_HID * 5; idx += TPB) {
        bp[idx] = OMEGA * bh[idx];
    }
    __syncthreads();

    const int g = blockIdx.x * TPB + tid;    // quad index: points 4g..4g+3

    SinK K;
    K.magic  = splat2( 12582912.0f);
    K.nmagic = splat2(-12582912.0f);
    K.inv2pi = splat2( 0.15915494309189535f);
    K.n2pi   = splat2(-6.28318530717958648f);

    // coords: 12 consecutive floats -> 3x LDG.128; passthrough stored immediately
    const float4* c4p = (const float4*)coords;
    float4 q0 = c4p[3 * g + 0];
    float4 q1 = c4p[3 * g + 1];
    float4 q2 = c4p[3 * g + 2];
    float4* cpass = (float4*)(out + N);
    cpass[3 * g + 0] = q0;
    cpass[3 * g + 1] = q1;
    cpass[3 * g + 2] = q2;

    u64 a_c0 = pack2(q0.x, q0.w);  // stream A: points 0,1
    u64 a_c1 = pack2(q0.y, q1.x);
    u64 a_c2 = pack2(q0.z, q1.y);
    u64 b_c0 = pack2(q1.z, q2.y);  // stream B: points 2,3
    u64 b_c1 = pack2(q1.w, q2.z);
    u64 b_c2 = pack2(q2.x, q2.w);

    // first layer (weights direct from global; cold path)
    u64 xa[HID], xb[HID], ya[HID], yb[HID];
    {
#pragma unroll
        for (int j = 0; j < HID; j++) {
            u64 bj = splat2(OMEGA * bf[j]);
            u64 w0 = splat2(OMEGA * Wf[j * IN_F + 0]);
            u64 w1 = splat2(OMEGA * Wf[j * IN_F + 1]);
            u64 w2 = splat2(OMEGA * Wf[j * IN_F + 2]);
            u64 a = fma2(w0, a_c0, bj);
            u64 b = fma2(w0, b_c0, bj);
            a = fma2(w1, a_c1, a);  b = fma2(w1, b_c1, b);
            a = fma2(w2, a_c2, a);  b = fma2(w2, b_c2, b);
            ya[j] = a; yb[j] = b;
        }
        sin5(xa, ya, K);     // A activation (pre-hidden)
        sin5(xb, yb, K);     // B activation (pre-hidden)
    }

    // enter skewed state: yA = pre-act of hidden layer 0 for A; xB = B's input to layer 0
    matvec5(ya, xa, wp, bp);

    // skewed mainloop: body(i) = sinA(i) || matvecB(i), then sinB(i) || matvecA(i+1)
    const u64*   L = wp;
    const float* B = bp;
#pragma unroll 1
    for (int i = 0; i < N_HID - 1; i++) {
        sin5(xa, ya, K);                 // MUFU, depends on ya
        matvec5(yb, xb, L, B);           // FMA,  independent -> overlaps
        sin5(xb, yb, K);                 // MUFU
        matvec5(ya, xa, L + 25, B + 5);  // FMA,  independent -> overlaps
        L += 25;
        B += 5;
    }
    // peel last layer (i = 255): no next-layer matvec for A
    sin5(xa, ya, K);
    matvec5(yb, xb, L, B);
    sin5(xb, yb, K);

    // final linear (weights direct from global)
    u64 oa = splat2(bl[0]), ob = oa;
#pragma unroll
    for (int j = 0; j < HID; j++) {
        u64 gj = splat2(Wl[j]);
        oa = fma2(gj, xa[j], oa);
        ob = fma2(gj, xb[j], ob);
    }

    float2 fa = unpack2(oa), fb = unpack2(ob);
    ((float4*)out)[g] = make_float4(fa.x, fa.y, fb.x, fb.y);
}

extern "C" void kernel_launch(void* const* d_in, const int* in_sizes, int n_in,
                              void* d_out, int out_size)
{
    const float* coords = (const float*)d_in[0];
    const float* Wf     = (const float*)d_in[1];
    const float* bf     = (const float*)d_in[2];
    const float* Wh     = (const float*)d_in[3];
    const float* bh     = (const float*)d_in[4];
    const float* Wl     = (const float*)d_in[5];
    const float* bl     = (const float*)d_in[6];
    float* out = (float*)d_out;

    const int N = in_sizes[0] / IN_F;               // 524288
    const int quads = N / 4;                        // 131072
    const int blocks = quads / TPB;                 // 512, exact

    cudaFuncSetAttribute(siren_kernel, cudaFuncAttributeMaxDynamicSharedMemorySize, SMEM_BYTES);
    siren_kernel<<<blocks, TPB, SMEM_BYTES>>>(coords, Wf, bf, Wh, bh, Wl, bl, out, N);
}

// round 7
// speedup vs baseline: 2.1398x; 2.1398x over previous
#include <cuda_runtime.h>

// SIREN: N pts, 3 -> 5 (sine) -> 256 x [5 -> 5 (sine)] -> 1 linear.
// Output: [out (N) | coords passthrough (3N)].
// 4 pts/thread as 2 f32x2 streams with ONE-LAYER SKEW (sinA || matvecB overlap
// of MUFU and FMA pipes). Explicit scalar u64 state, 3 blocks/SM (84-reg budget)
// so nothing spills. Weights + biases as dup-pairs in smem (LDS.64 broadcast).

typedef unsigned long long u64;
typedef unsigned int u32;

static constexpr int IN_F  = 3;
static constexpr int HID   = 5;
static constexpr int N_HID = 256;
static constexpr float OMEGA = 30.0f;
static constexpr int TPB = 256;

// smem: [0, 51200) 256 x 25 weight dup-pairs; [51200, 61440) 256 x 5 bias dup-pairs
static constexpr int W_U64      = N_HID * 25;
static constexpr int SMEM_BYTES = (W_U64 + N_HID * 5) * 8;   // 61440

__device__ __forceinline__ u64 fma2(u64 a, u64 b, u64 c) {
    u64 d; asm("fma.rn.f32x2 %0, %1, %2, %3;" : "=l"(d) : "l"(a), "l"(b), "l"(c)); return d;
}
__device__ __forceinline__ u64 add2(u64 a, u64 b) {
    u64 d; asm("add.rn.f32x2 %0, %1, %2;" : "=l"(d) : "l"(a), "l"(b)); return d;
}
__device__ __forceinline__ u64 pack2(float a, float b) {
    u64 d; asm("mov.b64 %0, {%1, %2};" : "=l"(d) : "f"(a), "f"(b)); return d;
}
__device__ __forceinline__ u64 splat2(float a) {
    u64 d; asm("mov.b64 %0, {%1, %1};" : "=l"(d) : "f"(a)); return d;
}
__device__ __forceinline__ float2 unpack2(u64 d) {
    float2 f; asm("mov.b64 {%0, %1}, %2;" : "=f"(f.x), "=f"(f.y) : "l"(d)); return f;
}
__device__ __forceinline__ float sinap(float x) {
    float s; asm("sin.approx.f32 %0, %1;" : "=f"(s) : "f"(x)); return s;
}

struct SinK { u64 magic, nmagic, inv2pi, n2pi; };

// sin of both lanes: 1-term CW reduction mod 2pi into [-pi,pi], MUFU sine.
__device__ __forceinline__ u64 sin2m(u64 y, const SinK& K) {
    u64 t  = fma2(y, K.inv2pi, K.magic);
    u64 fj = add2(t, K.nmagic);
    u64 r  = fma2(fj, K.n2pi, y);
    float2 rf = unpack2(r);
    return pack2(sinap(rf.x), sinap(rf.y));
}

// x_j = sin(y_j), 5-wide, explicit scalars
#define SIN5(X0,X1,X2,X3,X4, Y0,Y1,Y2,Y3,Y4)      \
    X0 = sin2m(Y0, K); X1 = sin2m(Y1, K);         \
    X2 = sin2m(Y2, K); X3 = sin2m(Y3, K);         \
    X4 = sin2m(Y4, K);

// y = W x + b; Lp: 25 w dup-pairs (k-major), Bp: 5 bias dup-pairs
#define MV5(Y0,Y1,Y2,Y3,Y4, X0,X1,X2,X3,X4, Lp, Bp)                         \
    Y0 = fma2((Lp)[ 0], X0, (Bp)[0]); Y1 = fma2((Lp)[ 1], X0, (Bp)[1]);    \
    Y2 = fma2((Lp)[ 2], X0, (Bp)[2]); Y3 = fma2((Lp)[ 3], X0, (Bp)[3]);    \
    Y4 = fma2((Lp)[ 4], X0, (Bp)[4]);                                       \
    Y0 = fma2((Lp)[ 5], X1, Y0); Y1 = fma2((Lp)[ 6], X1, Y1);              \
    Y2 = fma2((Lp)[ 7], X1, Y2); Y3 = fma2((Lp)[ 8], X1, Y3);              \
    Y4 = fma2((Lp)[ 9], X1, Y4);                                            \
    Y0 = fma2((Lp)[10], X2, Y0); Y1 = fma2((Lp)[11], X2, Y1);              \
    Y2 = fma2((Lp)[12], X2, Y2); Y3 = fma2((Lp)[13], X2, Y3);              \
    Y4 = fma2((Lp)[14], X2, Y4);                                            \
    Y0 = fma2((Lp)[15], X3, Y0); Y1 = fma2((Lp)[16], X3, Y1);              \
    Y2 = fma2((Lp)[17], X3, Y2); Y3 = fma2((Lp)[18], X3, Y3);              \
    Y4 = fma2((Lp)[19], X3, Y4);                                            \
    Y0 = fma2((Lp)[20], X4, Y0); Y1 = fma2((Lp)[21], X4, Y1);              \
    Y2 = fma2((Lp)[22], X4, Y2); Y3 = fma2((Lp)[23], X4, Y3);              \
    Y4 = fma2((Lp)[24], X4, Y4);

__global__ void __launch_bounds__(TPB, 3)
siren_kernel(const float* __restrict__ coords,
             const float* __restrict__ Wf, const float* __restrict__ bf,
             const float* __restrict__ Wh, const float* __restrict__ bh,
             const float* __restrict__ Wl, const float* __restrict__ bl,
             float* __restrict__ out, int N)
{
    extern __shared__ float smem[];
    u64* wp = (u64*)smem;                    // 25 pairs/layer
    u64* bp = wp + W_U64;                    // 5 pairs/layer

    const int tid = threadIdx.x;
    for (int idx = tid; idx < N_HID * 25; idx += TPB) {
        int l = idx / 25, r = idx % 25;
        int j = r / 5, k = r % 5;
        wp[l * 25 + k * 5 + j] = splat2(OMEGA * Wh[l * 25 + j * 5 + k]);
    }
    for (int idx = tid; idx < N_HID * 5; idx += TPB) {
        bp[idx] = splat2(OMEGA * bh[idx]);
    }
    __syncthreads();

    const int g = blockIdx.x * TPB + tid;    // quad index: points 4g..4g+3

    SinK K;
    K.magic  = splat2( 12582912.0f);
    K.nmagic = splat2(-12582912.0f);
    K.inv2pi = splat2( 0.15915494309189535f);
    K.n2pi   = splat2(-6.28318530717958648f);

    // coords: 12 consecutive floats -> 3x LDG.128; passthrough stored immediately
    const float4* c4p = (const float4*)coords;
    float4 q0 = c4p[3 * g + 0];
    float4 q1 = c4p[3 * g + 1];
    float4 q2 = c4p[3 * g + 2];
    float4* cpass = (float4*)(out + N);
    cpass[3 * g + 0] = q0;
    cpass[3 * g + 1] = q1;
    cpass[3 * g + 2] = q2;

    u64 a_c0 = pack2(q0.x, q0.w);  // stream A: points 0,1
    u64 a_c1 = pack2(q0.y, q1.x);
    u64 a_c2 = pack2(q0.z, q1.y);
    u64 b_c0 = pack2(q1.z, q2.y);  // stream B: points 2,3
    u64 b_c1 = pack2(q1.w, q2.z);
    u64 b_c2 = pack2(q2.x, q2.w);

    // first layer (weights direct from global; cold path)
    u64 xa0, xa1, xa2, xa3, xa4, ya0, ya1, ya2, ya3, ya4;
    u64 xb0, xb1, xb2, xb3, xb4, yb0, yb1, yb2, yb3, yb4;
    {
        u64 w, bj;
        bj = splat2(OMEGA * bf[0]);
        w = splat2(OMEGA * Wf[0]);  ya0 = fma2(w, a_c0, bj); yb0 = fma2(w, b_c0, bj);
        w = splat2(OMEGA * Wf[1]);  ya0 = fma2(w, a_c1, ya0); yb0 = fma2(w, b_c1, yb0);
        w = splat2(OMEGA * Wf[2]);  ya0 = fma2(w, a_c2, ya0); yb0 = fma2(w, b_c2, yb0);
        bj = splat2(OMEGA * bf[1]);
        w = splat2(OMEGA * Wf[3]);  ya1 = fma2(w, a_c0, bj); yb1 = fma2(w, b_c0, bj);
        w = splat2(OMEGA * Wf[4]);  ya1 = fma2(w, a_c1, ya1); yb1 = fma2(w, b_c1, yb1);
        w = splat2(OMEGA * Wf[5]);  ya1 = fma2(w, a_c2, ya1); yb1 = fma2(w, b_c2, yb1);
        bj = splat2(OMEGA * bf[2]);
        w = splat2(OMEGA * Wf[6]);  ya2 = fma2(w, a_c0, bj); yb2 = fma2(w, b_c0, bj);
        w = splat2(OMEGA * Wf[7]);  ya2 = fma2(w, a_c1, ya2); yb2 = fma2(w, b_c1, yb2);
        w = splat2(OMEGA * Wf[8]);  ya2 = fma2(w, a_c2, ya2); yb2 = fma2(w, b_c2, yb2);
        bj = splat2(OMEGA * bf[3]);
        w = splat2(OMEGA * Wf[9]);  ya3 = fma2(w, a_c0, bj); yb3 = fma2(w, b_c0, bj);
        w = splat2(OMEGA * Wf[10]); ya3 = fma2(w, a_c1, ya3); yb3 = fma2(w, b_c1, yb3);
        w = splat2(OMEGA * Wf[11]); ya3 = fma2(w, a_c2, ya3); yb3 = fma2(w, b_c2, yb3);
        bj = splat2(OMEGA * bf[4]);
        w = splat2(OMEGA * Wf[12]); ya4 = fma2(w, a_c0, bj); yb4 = fma2(w, b_c0, bj);
        w = splat2(OMEGA * Wf[13]); ya4 = fma2(w, a_c1, ya4); yb4 = fma2(w, b_c1, yb4);
        w = splat2(OMEGA * Wf[14]); ya4 = fma2(w, a_c2, ya4); yb4 = fma2(w, b_c2, yb4);
    }
    SIN5(xa0,xa1,xa2,xa3,xa4, ya0,ya1,ya2,ya3,ya4)
    SIN5(xb0,xb1,xb2,xb3,xb4, yb0,yb1,yb2,yb3,yb4)

    // enter skewed state: ya = pre-act of hidden layer 0 for stream A
    MV5(ya0,ya1,ya2,ya3,ya4, xa0,xa1,xa2,xa3,xa4, wp, bp)

    // skewed mainloop: sinA(i) || matvecB(i), then sinB(i) || matvecA(i+1)
    const u64* L  = wp;
    const u64* Bq = bp;
#pragma unroll 1
    for (int i = 0; i < N_HID - 1; i++) {
        SIN5(xa0,xa1,xa2,xa3,xa4, ya0,ya1,ya2,ya3,ya4)
        MV5(yb0,yb1,yb2,yb3,yb4, xb0,xb1,xb2,xb3,xb4, L, Bq)
        SIN5(xb0,xb1,xb2,xb3,xb4, yb0,yb1,yb2,yb3,yb4)
        MV5(ya0,ya1,ya2,ya3,ya4, xa0,xa1,xa2,xa3,xa4, L + 25, Bq + 5)
        L  += 25;
        Bq += 5;
    }
    // peel last layer (i = 255) — no next-layer matvec for A
    SIN5(xa0,xa1,xa2,xa3,xa4, ya0,ya1,ya2,ya3,ya4)
    MV5(yb0,yb1,yb2,yb3,yb4, xb0,xb1,xb2,xb3,xb4, L, Bq)
    SIN5(xb0,xb1,xb2,xb3,xb4, yb0,yb1,yb2,yb3,yb4)

    // final linear (weights direct from global)
    u64 oa = splat2(bl[0]), ob = oa;
    {
        u64 w;
        w = splat2(Wl[0]); oa = fma2(w, xa0, oa); ob = fma2(w, xb0, ob);
        w = splat2(Wl[1]); oa = fma2(w, xa1, oa); ob = fma2(w, xb1, ob);
        w = splat2(Wl[2]); oa = fma2(w, xa2, oa); ob = fma2(w, xb2, ob);
        w = splat2(Wl[3]); oa = fma2(w, xa3, oa); ob = fma2(w, xb3, ob);
        w = splat2(Wl[4]); oa = fma2(w, xa4, oa); ob = fma2(w, xb4, ob);
    }

    float2 fa = unpack2(oa), fb = unpack2(ob);
    ((float4*)out)[g] = make_float4(fa.x, fa.y, fb.x, fb.y);
}

extern "C" void kernel_launch(void* const* d_in, const int* in_sizes, int n_in,
                              void* d_out, int out_size)
{
    const float* coords = (const float*)d_in[0];
    const float* Wf     = (const float*)d_in[1];
    const float* bf     = (const float*)d_in[2];
    const float* Wh     = (const float*)d_in[3];
    const float* bh     = (const float*)d_in[4];
    const float* Wl     = (const float*)d_in[5];
    const float* bl     = (const float*)d_in[6];
    float* out = (float*)d_out;

    const int N = in_sizes[0] / IN_F;               // 524288
    const int quads = N / 4;                        // 131072
    const int blocks = quads / TPB;                 // 512, exact

    cudaFuncSetAttribute(siren_kernel, cudaFuncAttributeMaxDynamicSharedMemorySize, SMEM_BYTES);
    siren_kernel<<<blocks, TPB, SMEM_BYTES>>>(coords, Wf, bf, Wh, bh, Wl, bl, out, N);
}

// round 9
// speedup vs baseline: 2.9957x; 1.4000x over previous
#include <cuda_runtime.h>

// SIREN: N pts, 3 -> 5 (sine) -> 256 x [5 -> 5 (sine)] -> 1 linear.
// Output: [out (N) | coords passthrough (3N)].
// 4 pts/thread as 2 f32x2 packs. FFMA2 matvec; sine = raw MUFU sin.approx
// (built-in range reduction, |y| <= ~19). Per-warp start-time stagger breaks
// the MUFU/FMA phase lock across the 8 warps sharing each SMSP.

typedef unsigned long long u64;
typedef unsigned int u32;

static constexpr int IN_F  = 3;
static constexpr int HID   = 5;
static constexpr int N_HID = 256;
static constexpr float OMEGA = 30.0f;
static constexpr int TPB = 256;

// smem: [0, 51200) 256 layers x 25 w dup-pairs (u64); [51200, 56320) 256 x 5 bias scalars
static constexpr int BLOB_U64   = N_HID * 25;
static constexpr int SMEM_BYTES = BLOB_U64 * 8 + N_HID * 5 * 4;   // 56320

__device__ __forceinline__ u64 fma2(u64 a, u64 b, u64 c) {
    u64 d; asm("fma.rn.f32x2 %0, %1, %2, %3;" : "=l"(d) : "l"(a), "l"(b), "l"(c)); return d;
}
__device__ __forceinline__ u64 pack2(float a, float b) {
    u64 d; asm("mov.b64 %0, {%1, %2};" : "=l"(d) : "f"(a), "f"(b)); return d;
}
__device__ __forceinline__ u64 splat2(float a) {
    u64 d; asm("mov.b64 %0, {%1, %1};" : "=l"(d) : "f"(a)); return d;
}
__device__ __forceinline__ float2 unpack2(u64 d) {
    float2 f; asm("mov.b64 {%0, %1}, %2;" : "=f"(f.x), "=f"(f.y) : "l"(d)); return f;
}
__device__ __forceinline__ float sinap(float x) {
    float s; asm("sin.approx.f32 %0, %1;" : "=f"(s) : "f"(x)); return s;
}

// sin of both packed lanes: raw MUFU (hardware range reduction).
__device__ __forceinline__ u64 sin2m(u64 y) {
    float2 f = unpack2(y);
    return pack2(sinap(f.x), sinap(f.y));
}

__global__ void __launch_bounds__(TPB, 4)
siren_kernel(const float* __restrict__ coords,
             const float* __restrict__ Wf, const float* __restrict__ bf,
             const float* __restrict__ Wh, const float* __restrict__ bh,
             const float* __restrict__ Wl, const float* __restrict__ bl,
             float* __restrict__ out, int N)
{
    extern __shared__ float smem[];
    u64*   wp = (u64*)smem;                  // 25 pairs per layer
    float* bp = smem + BLOB_U64 * 2;         // 5 scalars per layer

    const int tid = threadIdx.x;
    for (int idx = tid; idx < N_HID * 25; idx += TPB) {
        int l = idx / 25, r = idx % 25;
        int j = r / 5, k = r % 5;
        wp[l * 25 + k * 5 + j] = splat2(OMEGA * Wh[l * 25 + j * 5 + k]);
    }
    for (int idx = tid; idx < N_HID * 5; idx += TPB) {
        bp[idx] = OMEGA * bh[idx];
    }
    __syncthreads();

    const int g = blockIdx.x * TPB + tid;    // quad index: points 4g..4g+3 (exact fit)

    // coords: 12 consecutive floats -> 3x LDG.128; passthrough stored immediately
    const float4* c4p = (const float4*)coords;
    float4 q0 = c4p[3 * g + 0];   // c0A c1A c2A c0B
    float4 q1 = c4p[3 * g + 1];   // c1B c2B c0C c1C
    float4 q2 = c4p[3 * g + 2];   // c2C c0D c1D c2D
    float4* cpass = (float4*)(out + N);
    cpass[3 * g + 0] = q0;
    cpass[3 * g + 1] = q1;
    cpass[3 * g + 2] = q2;

    u64 a_c0 = pack2(q0.x, q0.w);  // points A,B
    u64 a_c1 = pack2(q0.y, q1.x);
    u64 a_c2 = pack2(q0.z, q1.y);
    u64 b_c0 = pack2(q1.z, q2.y);  // points C,D
    u64 b_c1 = pack2(q1.w, q2.z);
    u64 b_c2 = pack2(q2.x, q2.w);

    // ---- warp desync: stagger the 8 warps that share each SMSP ----
    // SMSP id = wid & 3; co-resident same-SMSP warps: wid/4 (2 per block) x 4 blocks.
    {
        int slot = ((blockIdx.x & 3) << 1) | ((tid >> 5) >> 2);   // 0..7
        int iters = slot * 40;                                    // ~slot*160 cyc (FADD lat 4)
        float v = (float)tid;
#pragma unroll 1
        for (int i = 0; i < iters; i++) v += 1.0f;
        asm volatile("" :: "f"(v));     // keep the chain alive
    }

    // first layer: weights direct from global (L2 broadcast, cold path)
    u64 xa0, xa1, xa2, xa3, xa4, xb0, xb1, xb2, xb3, xb4;
    {
        u64 ya[HID], yb[HID];
#pragma unroll
        for (int j = 0; j < HID; j++) {
            u64 bj = splat2(OMEGA * bf[j]);
            u64 w0 = splat2(OMEGA * Wf[j * IN_F + 0]);
            u64 w1 = splat2(OMEGA * Wf[j * IN_F + 1]);
            u64 w2 = splat2(OMEGA * Wf[j * IN_F + 2]);
            u64 a = fma2(w0, a_c0, bj);
            u64 b = fma2(w0, b_c0, bj);
            a = fma2(w1, a_c1, a);  b = fma2(w1, b_c1, b);
            a = fma2(w2, a_c2, a);  b = fma2(w2, b_c2, b);
            ya[j] = a; yb[j] = b;
        }
        xa0 = sin2m(ya[0]); xa1 = sin2m(ya[1]); xa2 = sin2m(ya[2]);
        xa3 = sin2m(ya[3]); xa4 = sin2m(ya[4]);
        xb0 = sin2m(yb[0]); xb1 = sin2m(yb[1]); xb2 = sin2m(yb[2]);
        xb3 = sin2m(yb[3]); xb4 = sin2m(yb[4]);
    }

    // 256 hidden layers
    const u64*   L = wp;
    const float* B = bp;
#pragma unroll 1
    for (int l = 0; l < N_HID; l++) {
        u64 w;
        u64 b0 = splat2(B[0]), b1 = splat2(B[1]), b2 = splat2(B[2]),
            b3 = splat2(B[3]), b4 = splat2(B[4]);
        u64 ya0, ya1, ya2, ya3, ya4, yb0, yb1, yb2, yb3, yb4;
        w = L[ 0]; ya0 = fma2(w, xa0, b0); yb0 = fma2(w, xb0, b0);
        w = L[ 1]; ya1 = fma2(w, xa0, b1); yb1 = fma2(w, xb0, b1);
        w = L[ 2]; ya2 = fma2(w, xa0, b2); yb2 = fma2(w, xb0, b2);
        w = L[ 3]; ya3 = fma2(w, xa0, b3); yb3 = fma2(w, xb0, b3);
        w = L[ 4]; ya4 = fma2(w, xa0, b4); yb4 = fma2(w, xb0, b4);
        w = L[ 5]; ya0 = fma2(w, xa1, ya0); yb0 = fma2(w, xb1, yb0);
        w = L[ 6]; ya1 = fma2(w, xa1, ya1); yb1 = fma2(w, xb1, yb1);
        w = L[ 7]; ya2 = fma2(w, xa1, ya2); yb2 = fma2(w, xb1, yb2);
        w = L[ 8]; ya3 = fma2(w, xa1, ya3); yb3 = fma2(w, xb1, yb3);
        w = L[ 9]; ya4 = fma2(w, xa1, ya4); yb4 = fma2(w, xb1, yb4);
        w = L[10]; ya0 = fma2(w, xa2, ya0); yb0 = fma2(w, xb2, yb0);
        w = L[11]; ya1 = fma2(w, xa2, ya1); yb1 = fma2(w, xb2, yb1);
        w = L[12]; ya2 = fma2(w, xa2, ya2); yb2 = fma2(w, xb2, yb2);
        w = L[13]; ya3 = fma2(w, xa2, ya3); yb3 = fma2(w, xb2, yb3);
        w = L[14]; ya4 = fma2(w, xa2, ya4); yb4 = fma2(w, xb2, yb4);
        w = L[15]; ya0 = fma2(w, xa3, ya0); yb0 = fma2(w, xb3, yb0);
        w = L[16]; ya1 = fma2(w, xa3, ya1); yb1 = fma2(w, xb3, yb1);
        w = L[17]; ya2 = fma2(w, xa3, ya2); yb2 = fma2(w, xb3, yb2);
        w = L[18]; ya3 = fma2(w, xa3, ya3); yb3 = fma2(w, xb3, yb3);
        w = L[19]; ya4 = fma2(w, xa3, ya4); yb4 = fma2(w, xb3, yb4);
        w = L[20]; ya0 = fma2(w, xa4, ya0); yb0 = fma2(w, xb4, yb0);
        w = L[21]; ya1 = fma2(w, xa4, ya1); yb1 = fma2(w, xb4, yb1);
        w = L[22]; ya2 = fma2(w, xa4, ya2); yb2 = fma2(w, xb4, yb2);
        w = L[23]; ya3 = fma2(w, xa4, ya3); yb3 = fma2(w, xb4, yb3);
        w = L[24]; ya4 = fma2(w, xa4, ya4); yb4 = fma2(w, xb4, yb4);
        xa0 = sin2m(ya0); xa1 = sin2m(ya1); xa2 = sin2m(ya2);
        xa3 = sin2m(ya3); xa4 = sin2m(ya4);
        xb0 = sin2m(yb0); xb1 = sin2m(yb1); xb2 = sin2m(yb2);
        xb3 = sin2m(yb3); xb4 = sin2m(yb4);
        L += 25;
        B += 5;
    }

    // final linear: weights direct from global
    u64 g0 = splat2(Wl[0]), g1 = splat2(Wl[1]), g2 = splat2(Wl[2]),
        g3 = splat2(Wl[3]), g4 = splat2(Wl[4]);
    u64 ob0 = splat2(bl[0]);
    u64 oa = fma2(g0, xa0, ob0), ob = fma2(g0, xb0, ob0);
    oa = fma2(g1, xa1, oa); ob = fma2(g1, xb1, ob);
    oa = fma2(g2, xa2, oa); ob = fma2(g2, xb2, ob);
    oa = fma2(g3, xa3, oa); ob = fma2(g3, xb3, ob);
    oa = fma2(g4, xa4, oa); ob = fma2(g4, xb4, ob);

    float2 fa = unpack2(oa), fb = unpack2(ob);
    ((float4*)out)[g] = make_float4(fa.x, fa.y, fb.x, fb.y);
}

extern "C" void kernel_launch(void* const* d_in, const int* in_sizes, int n_in,
                              void* d_out, int out_size)
{
    const float* coords = (const float*)d_in[0];
    const float* Wf     = (const float*)d_in[1];
    const float* bf     = (const float*)d_in[2];
    const float* Wh     = (const float*)d_in[3];
    const float* bh     = (const float*)d_in[4];
    const float* Wl     = (const float*)d_in[5];
    const float* bl     = (const float*)d_in[6];
    float* out = (float*)d_out;

    const int N = in_sizes[0] / IN_F;               // 524288
    const int quads = N / 4;                        // 131072
    const int blocks = quads / TPB;                 // 512, exact

    cudaFuncSetAttribute(siren_kernel, cudaFuncAttributeMaxDynamicSharedMemorySize, SMEM_BYTES);
    siren_kernel<<<blocks, TPB, SMEM_BYTES>>>(coords, Wf, bf, Wh, bh, Wl, bl, out, N);
}